// round 8
// baseline (speedup 1.0000x reference)
#include <cuda_runtime.h>
#include <math.h>
#include <stdint.h>

#define D_MODEL 1024
#define NHEADS  16
#define DKH     64
#define BATCH   4
#define SEQ     2048
#define MT      (BATCH*SEQ)   // 8192 rows

// ---------------- scratch (device globals; no cudaMalloc allowed) ----------
__device__ float g_q[(size_t)MT * D_MODEL];
__device__ float g_k[(size_t)MT * D_MODEL];
__device__ float g_v[(size_t)MT * D_MODEL];
__device__ float g_ctx[(size_t)MT * D_MODEL];
__device__ float2 g_rope[(size_t)SEQ * 32];   // [s][k] -> (cos, sin)

// ---------------- helpers ---------------------------------------------------
__device__ __forceinline__ uint32_t f2tf(float x) {
    uint32_t r;
    asm("cvt.rna.tf32.f32 %0, %1;" : "=r"(r) : "f"(x));
    return r;
}

__device__ __forceinline__ void mma_tf32_p(
    float* c,
    uint32_t a0, uint32_t a1, uint32_t a2, uint32_t a3,
    uint32_t b0, uint32_t b1)
{
    asm volatile(
        "mma.sync.aligned.m16n8k8.row.col.f32.tf32.tf32.f32 "
        "{%0,%1,%2,%3},{%4,%5,%6,%7},{%8,%9},{%0,%1,%2,%3};"
        : "+f"(c[0]), "+f"(c[1]), "+f"(c[2]), "+f"(c[3])
        : "r"(a0), "r"(a1), "r"(a2), "r"(a3), "r"(b0), "r"(b1));
}

__device__ __forceinline__ int swz(int r) { return (r & 3) ^ ((r >> 2) & 3); }

// ---------------- RoPE cos/sin table ---------------------------------------
__global__ void rope_table_kernel(const int* __restrict__ pos32)
{
    int idx = blockIdx.x * 256 + threadIdx.x;
    if (idx >= SEQ * 32) return;
    int s = idx >> 5;
    int k = idx & 31;
    const bool is64 = (pos32[1] == 0 && pos32[2] == 1);
    long long pv = is64 ? ((const long long*)pos32)[s] : (long long)pos32[s];
    float p   = (float)pv;
    float inv = powf(10000.0f, -(float)k * (1.0f / 32.0f));
    float sn, cs;
    sincosf(p * inv, &sn, &cs);
    g_rope[idx] = make_float2(cs, sn);
}

// ---------------- tf32 GEMM: C[m,n] = sum_d A[m,d] * W[n,d]  (NT) -----------
// 128x128 tile, BK=16, 256 thr = 8 warps (4m x 2n), warp tile 32x64.
// smem word(r,k) = r*16 + 4*((k&3)^swz(r)) + (k>>2); fragments = 1 LDS.128.
// rope!=0: apply RoPE rotation in the epilogue for blockIdx.z < 2 (Q and K).
__global__ __launch_bounds__(256) void gemm_tf32_kernel(
    const float* __restrict__ A,
    const float* __restrict__ W0, const float* __restrict__ W1, const float* __restrict__ W2,
    float* __restrict__ C0, float* __restrict__ C1, float* __restrict__ C2,
    int rope)
{
    const float* W; float* C;
    if (blockIdx.z == 0)      { W = W0; C = C0; }
    else if (blockIdx.z == 1) { W = W1; C = C1; }
    else                      { W = W2; C = C2; }

    __shared__ uint32_t As[2][128 * 16];
    __shared__ uint32_t Ws[2][128 * 16];

    const int tid = threadIdx.x;
    const int w  = tid >> 5;
    const int l  = tid & 31;
    const int g  = l >> 2;
    const int tg = l & 3;
    const int m0 = blockIdx.y * 128;
    const int n0 = blockIdx.x * 128;
    const int wm = (w & 3) * 32;
    const int wn = (w >> 2) * 64;

    const int lr = tid >> 1;          // 0..127
    const int lc = (tid & 1) * 8;     // 0 or 8
    const float* Ag = A + (size_t)(m0 + lr) * D_MODEL + lc;
    const float* Wg = W + (size_t)(n0 + lr) * D_MODEL + lc;
    const int srx = swz(lr);
    const int sb  = lr * 16 + (lc >> 2);
    const int e0 = 4 * (0 ^ srx), e1 = 4 * (1 ^ srx), e2 = 4 * (2 ^ srx), e3 = 4 * (3 ^ srx);

    int aoff[2][2], boff[8];
#pragma unroll
    for (int mi = 0; mi < 2; mi++)
#pragma unroll
        for (int hf = 0; hf < 2; hf++) {
            int row = wm + 16 * mi + 8 * hf + g;
            aoff[mi][hf] = row * 16 + 4 * (tg ^ swz(row));
        }
#pragma unroll
    for (int ni = 0; ni < 8; ni++) {
        int row = wn + 8 * ni + g;
        boff[ni] = row * 16 + 4 * (tg ^ swz(row));
    }

    float acc[2][8][4];
#pragma unroll
    for (int mi = 0; mi < 2; mi++)
#pragma unroll
        for (int ni = 0; ni < 8; ni++)
#pragma unroll
            for (int j = 0; j < 4; j++) acc[mi][ni][j] = 0.0f;

    float4 a0v = *(const float4*)Ag;
    float4 a1v = *(const float4*)(Ag + 4);
    float4 w0v = *(const float4*)Wg;
    float4 w1v = *(const float4*)(Wg + 4);

#pragma unroll 1
    for (int t = 0; t < D_MODEL / 16; t++) {
        const int buf = t & 1;
        {
            uint32_t* Ab = As[buf];
            uint32_t* Wb = Ws[buf];
            Ab[sb + e0]     = f2tf(a0v.x);
            Ab[sb + e1]     = f2tf(a0v.y);
            Ab[sb + e2]     = f2tf(a0v.z);
            Ab[sb + e3]     = f2tf(a0v.w);
            Ab[sb + e0 + 1] = f2tf(a1v.x);
            Ab[sb + e1 + 1] = f2tf(a1v.y);
            Ab[sb + e2 + 1] = f2tf(a1v.z);
            Ab[sb + e3 + 1] = f2tf(a1v.w);
            Wb[sb + e0]     = f2tf(w0v.x);
            Wb[sb + e1]     = f2tf(w0v.y);
            Wb[sb + e2]     = f2tf(w0v.z);
            Wb[sb + e3]     = f2tf(w0v.w);
            Wb[sb + e0 + 1] = f2tf(w1v.x);
            Wb[sb + e1 + 1] = f2tf(w1v.y);
            Wb[sb + e2 + 1] = f2tf(w1v.z);
            Wb[sb + e3 + 1] = f2tf(w1v.w);
        }
        __syncthreads();

        if (t + 1 < D_MODEL / 16) {
            const float* An = Ag + (t + 1) * 16;
            const float* Wn = Wg + (t + 1) * 16;
            a0v = *(const float4*)An;
            a1v = *(const float4*)(An + 4);
            w0v = *(const float4*)Wn;
            w1v = *(const float4*)(Wn + 4);
        }

        {
            const uint32_t* Ab = As[buf];
            const uint32_t* Wb = Ws[buf];
            uint4 af[2][2], bf[8];
#pragma unroll
            for (int mi = 0; mi < 2; mi++) {
                af[mi][0] = *(const uint4*)&Ab[aoff[mi][0]];
                af[mi][1] = *(const uint4*)&Ab[aoff[mi][1]];
            }
#pragma unroll
            for (int ni = 0; ni < 8; ni++)
                bf[ni] = *(const uint4*)&Wb[boff[ni]];

#pragma unroll
            for (int mi = 0; mi < 2; mi++)
#pragma unroll
                for (int ni = 0; ni < 8; ni++) {
                    mma_tf32_p(acc[mi][ni],
                               af[mi][0].x, af[mi][1].x, af[mi][0].y, af[mi][1].y,
                               bf[ni].x, bf[ni].y);
                    mma_tf32_p(acc[mi][ni],
                               af[mi][0].z, af[mi][1].z, af[mi][0].w, af[mi][1].w,
                               bf[ni].z, bf[ni].w);
                }
        }
    }

    // fused RoPE (Q and K only): each thread's col pair (2tg, 2tg+1) within an
    // 8ni group is one rotation pair of one head (n offsets are 64-aligned).
    if (rope && blockIdx.z < 2) {
#pragma unroll
        for (int mi = 0; mi < 2; mi++) {
            const int s0 = (m0 + wm + 16 * mi + g) % SEQ;   // row0 % SEQ
            const int s1 = s0 + 8;                          // row1 (no 2048 wrap: block-aligned)
#pragma unroll
            for (int ni = 0; ni < 8; ni++) {
                const int k = ((wn + 8 * ni + 2 * tg) & 63) >> 1;
                float2 cs0 = g_rope[s0 * 32 + k];
                float2 cs1 = g_rope[s1 * 32 + k];
                float xe0 = acc[mi][ni][0], xo0 = acc[mi][ni][1];
                float xe1 = acc[mi][ni][2], xo1 = acc[mi][ni][3];
                acc[mi][ni][0] = cs0.x * xe0 - cs0.y * xo0;
                acc[mi][ni][1] = cs0.y * xe0 + cs0.x * xo0;
                acc[mi][ni][2] = cs1.x * xe1 - cs1.y * xo1;
                acc[mi][ni][3] = cs1.y * xe1 + cs1.x * xo1;
            }
        }
    }

#pragma unroll
    for (int mi = 0; mi < 2; mi++) {
        const size_t row0 = (size_t)(m0 + wm + 16 * mi + g);
        const size_t row1 = row0 + 8;
#pragma unroll
        for (int ni = 0; ni < 8; ni++) {
            const int col = n0 + wn + 8 * ni + 2 * tg;
            *(float2*)(C + row0 * D_MODEL + col) = make_float2(acc[mi][ni][0], acc[mi][ni][1]);
            *(float2*)(C + row1 * D_MODEL + col) = make_float2(acc[mi][ni][2], acc[mi][ni][3]);
        }
    }
}

// ---------------- tf32 tensor-core flash attention -------------------------
// smem (uint32 words): Ks[64][68], Vs[64][72], Ps[64][68]
#define KS_STRIDE 68
#define VS_STRIDE 72
#define PS_STRIDE 68
#define ATTN_SMEM_W (64*KS_STRIDE + 64*VS_STRIDE + 64*PS_STRIDE)
#define ATTN_SMEM_B (ATTN_SMEM_W * 4)

__device__ __forceinline__ void mma_tf32(
    float& c0, float& c1, float& c2, float& c3,
    uint32_t a0, uint32_t a1, uint32_t a2, uint32_t a3,
    uint32_t b0, uint32_t b1)
{
    asm volatile(
        "mma.sync.aligned.m16n8k8.row.col.f32.tf32.tf32.f32 "
        "{%0,%1,%2,%3},{%4,%5,%6,%7},{%8,%9},{%0,%1,%2,%3};"
        : "+f"(c0), "+f"(c1), "+f"(c2), "+f"(c3)
        : "r"(a0), "r"(a1), "r"(a2), "r"(a3), "r"(b0), "r"(b1));
}

__global__ __launch_bounds__(128) void attn_tf32_kernel()
{
    extern __shared__ uint32_t smu[];
    uint32_t* Ks = smu;                                  // [64][68]
    uint32_t* Vs = smu + 64 * KS_STRIDE;                 // [64][72]
    uint32_t* Ps = smu + 64 * KS_STRIDE + 64 * VS_STRIDE;// [64][68]

    const int qb = blockIdx.x, h = blockIdx.y, b = blockIdx.z;
    const int q0 = qb * 64;
    const int tid = threadIdx.x;
    const int w  = tid >> 5;
    const int l  = tid & 31;
    const int g  = l >> 2;
    const int tg = l & 3;

    const float* Qg = g_q + ((size_t)(b * SEQ + q0)) * D_MODEL + h * DKH;
    const float* Kg = g_k + ((size_t)b * SEQ) * D_MODEL + h * DKH;
    const float* Vg = g_v + ((size_t)b * SEQ) * D_MODEL + h * DKH;

    uint32_t qa[8][4];
    {
        const float* r0 = Qg + (size_t)(16 * w + g) * D_MODEL;
        const float* r1 = Qg + (size_t)(16 * w + g + 8) * D_MODEL;
#pragma unroll
        for (int kc = 0; kc < 8; kc++) {
            qa[kc][0] = f2tf(r0[8 * kc + tg]);
            qa[kc][1] = f2tf(r1[8 * kc + tg]);
            qa[kc][2] = f2tf(r0[8 * kc + tg + 4]);
            qa[kc][3] = f2tf(r1[8 * kc + tg + 4]);
        }
    }

    float o[8][4];
#pragma unroll
    for (int dc = 0; dc < 8; dc++)
#pragma unroll
        for (int j = 0; j < 4; j++) o[dc][j] = 0.0f;
    float m0 = -1e30f, m1 = -1e30f, l0 = 0.0f, l1 = 0.0f;

    for (int kb = 0; kb <= qb; kb++) {
        const int k0 = kb * 64;
        __syncthreads();
#pragma unroll
        for (int i = 0; i < 8; i++) {
            int idx = tid + 128 * i;
            int r   = idx >> 4;
            int c   = (idx & 15) * 4;
            float4 kv = *(const float4*)(Kg + (size_t)(k0 + r) * D_MODEL + c);
            float4 vv = *(const float4*)(Vg + (size_t)(k0 + r) * D_MODEL + c);
            uint4 kt = make_uint4(f2tf(kv.x), f2tf(kv.y), f2tf(kv.z), f2tf(kv.w));
            uint4 vt = make_uint4(f2tf(vv.x), f2tf(vv.y), f2tf(vv.z), f2tf(vv.w));
            *(uint4*)&Ks[r * KS_STRIDE + c] = kt;
            *(uint4*)&Vs[r * VS_STRIDE + c] = vt;
        }
        __syncthreads();

        float s[8][4];
#pragma unroll
        for (int nc = 0; nc < 8; nc++)
#pragma unroll
            for (int j = 0; j < 4; j++) s[nc][j] = 0.0f;

#pragma unroll
        for (int nc = 0; nc < 8; nc++) {
            const uint32_t* krow = &Ks[(8 * nc + g) * KS_STRIDE];
#pragma unroll
            for (int kc = 0; kc < 8; kc++) {
                uint32_t b0 = krow[8 * kc + tg];
                uint32_t b1 = krow[8 * kc + tg + 4];
                mma_tf32(s[nc][0], s[nc][1], s[nc][2], s[nc][3],
                         qa[kc][0], qa[kc][1], qa[kc][2], qa[kc][3], b0, b1);
            }
        }

#pragma unroll
        for (int nc = 0; nc < 8; nc++)
#pragma unroll
            for (int j = 0; j < 4; j++) s[nc][j] *= 0.125f;

        if (kb == qb) {
            const int r0 = 16 * w + g, r1 = r0 + 8;
#pragma unroll
            for (int nc = 0; nc < 8; nc++) {
                int c0 = 8 * nc + 2 * tg, c1 = c0 + 1;
                if (c0 > r0) s[nc][0] = -1e30f;
                if (c1 > r0) s[nc][1] = -1e30f;
                if (c0 > r1) s[nc][2] = -1e30f;
                if (c1 > r1) s[nc][3] = -1e30f;
            }
        }

        float rm0 = -1e30f, rm1 = -1e30f;
#pragma unroll
        for (int nc = 0; nc < 8; nc++) {
            rm0 = fmaxf(rm0, fmaxf(s[nc][0], s[nc][1]));
            rm1 = fmaxf(rm1, fmaxf(s[nc][2], s[nc][3]));
        }
        rm0 = fmaxf(rm0, __shfl_xor_sync(0xffffffffu, rm0, 1));
        rm0 = fmaxf(rm0, __shfl_xor_sync(0xffffffffu, rm0, 2));
        rm1 = fmaxf(rm1, __shfl_xor_sync(0xffffffffu, rm1, 1));
        rm1 = fmaxf(rm1, __shfl_xor_sync(0xffffffffu, rm1, 2));

        float mn0 = fmaxf(m0, rm0), mn1 = fmaxf(m1, rm1);
        float al0 = __expf(m0 - mn0), al1 = __expf(m1 - mn1);
        m0 = mn0; m1 = mn1;

        float rs0 = 0.0f, rs1 = 0.0f;
#pragma unroll
        for (int nc = 0; nc < 8; nc++) {
            float p0 = __expf(s[nc][0] - mn0);
            float p1 = __expf(s[nc][1] - mn0);
            float p2 = __expf(s[nc][2] - mn1);
            float p3 = __expf(s[nc][3] - mn1);
            s[nc][0] = p0; s[nc][1] = p1; s[nc][2] = p2; s[nc][3] = p3;
            rs0 += p0 + p1; rs1 += p2 + p3;
        }
        rs0 += __shfl_xor_sync(0xffffffffu, rs0, 1);
        rs0 += __shfl_xor_sync(0xffffffffu, rs0, 2);
        rs1 += __shfl_xor_sync(0xffffffffu, rs1, 1);
        rs1 += __shfl_xor_sync(0xffffffffu, rs1, 2);
        l0 = l0 * al0 + rs0;
        l1 = l1 * al1 + rs1;

#pragma unroll
        for (int dc = 0; dc < 8; dc++) {
            o[dc][0] *= al0; o[dc][1] *= al0;
            o[dc][2] *= al1; o[dc][3] *= al1;
        }

        {
            const int r0 = 16 * w + g, r1 = r0 + 8;
#pragma unroll
            for (int nc = 0; nc < 8; nc++) {
                uint2 p01 = make_uint2(f2tf(s[nc][0]), f2tf(s[nc][1]));
                uint2 p23 = make_uint2(f2tf(s[nc][2]), f2tf(s[nc][3]));
                *(uint2*)&Ps[r0 * PS_STRIDE + 8 * nc + 2 * tg] = p01;
                *(uint2*)&Ps[r1 * PS_STRIDE + 8 * nc + 2 * tg] = p23;
            }
        }
        __syncwarp();

        uint32_t pa[8][4];
        {
            const uint32_t* p0 = &Ps[(16 * w + g) * PS_STRIDE];
            const uint32_t* p1 = &Ps[(16 * w + g + 8) * PS_STRIDE];
#pragma unroll
            for (int nc = 0; nc < 8; nc++) {
                pa[nc][0] = p0[8 * nc + tg];
                pa[nc][1] = p1[8 * nc + tg];
                pa[nc][2] = p0[8 * nc + tg + 4];
                pa[nc][3] = p1[8 * nc + tg + 4];
            }
        }

#pragma unroll
        for (int dc = 0; dc < 8; dc++) {
#pragma unroll
            for (int nc = 0; nc < 8; nc++) {
                uint32_t b0 = Vs[(8 * nc + tg) * VS_STRIDE + 8 * dc + g];
                uint32_t b1 = Vs[(8 * nc + tg + 4) * VS_STRIDE + 8 * dc + g];
                mma_tf32(o[dc][0], o[dc][1], o[dc][2], o[dc][3],
                         pa[nc][0], pa[nc][1], pa[nc][2], pa[nc][3], b0, b1);
            }
        }
    }

    float* Og = g_ctx + ((size_t)(b * SEQ + q0)) * D_MODEL + h * DKH;
    float il0 = 1.0f / l0, il1 = 1.0f / l1;
    float* w0 = Og + (size_t)(16 * w + g) * D_MODEL;
    float* w1 = Og + (size_t)(16 * w + g + 8) * D_MODEL;
#pragma unroll
    for (int dc = 0; dc < 8; dc++) {
        *(float2*)(w0 + 8 * dc + 2 * tg) = make_float2(o[dc][0] * il0, o[dc][1] * il0);
        *(float2*)(w1 + 8 * dc + 2 * tg) = make_float2(o[dc][2] * il1, o[dc][3] * il1);
    }
}

// ---------------- launch ---------------------------------------------------
extern "C" void kernel_launch(void* const* d_in, const int* in_sizes, int n_in,
                              void* d_out, int out_size)
{
    const float*      X   = (const float*)d_in[0];
    const int*        pos = (const int*)d_in[1];
    const float*      Wq  = (const float*)d_in[2];
    const float*      Wk  = (const float*)d_in[3];
    const float*      Wv  = (const float*)d_in[4];
    const float*      Wo  = (const float*)d_in[5];
    float*            out = (float*)d_out;

    float *dq, *dk, *dv, *dctx;
    cudaGetSymbolAddress((void**)&dq,   g_q);
    cudaGetSymbolAddress((void**)&dk,   g_k);
    cudaGetSymbolAddress((void**)&dv,   g_v);
    cudaGetSymbolAddress((void**)&dctx, g_ctx);

    // RoPE cos/sin table
    rope_table_kernel<<<(SEQ * 32 + 255) / 256, 256>>>(pos);

    // QKV projections (tf32 tensor cores) with fused RoPE on Q, K
    dim3 gqkv(D_MODEL / 128, MT / 128, 3);
    gemm_tf32_kernel<<<gqkv, 256>>>(X, Wq, Wk, Wv, dq, dk, dv, 1);

    // causal attention (tf32 tensor cores)
    cudaFuncSetAttribute(attn_tf32_kernel, cudaFuncAttributeMaxDynamicSharedMemorySize, ATTN_SMEM_B);
    dim3 ga(SEQ / 64, NHEADS, BATCH);
    attn_tf32_kernel<<<ga, 128, ATTN_SMEM_B>>>();

    // output projection (tf32 tensor cores, no rope)
    dim3 go(D_MODEL / 128, MT / 128, 1);
    gemm_tf32_kernel<<<go, 256>>>(dctx, Wo, Wo, Wo, out, out, out, 0);
}

// round 11
// speedup vs baseline: 1.0434x; 1.0434x over previous
#include <cuda_runtime.h>
#include <math.h>
#include <stdint.h>

#define D_MODEL 1024
#define NHEADS  16
#define DKH     64
#define BATCH   4
#define SEQ     2048
#define MT      (BATCH*SEQ)   // 8192 rows

// ---------------- scratch (device globals; no cudaMalloc allowed) ----------
__device__ float g_q[(size_t)MT * D_MODEL];
__device__ float g_k[(size_t)MT * D_MODEL];
__device__ float g_v[(size_t)MT * D_MODEL];
__device__ float g_ctx[(size_t)MT * D_MODEL];
__device__ float2 g_rope[(size_t)SEQ * 32];   // [s][k] -> (cos, sin)

// ---------------- helpers ---------------------------------------------------
__device__ __forceinline__ uint32_t f2tf(float x) {
    uint32_t r;
    asm("cvt.rna.tf32.f32 %0, %1;" : "=r"(r) : "f"(x));
    return r;
}

__device__ __forceinline__ void mma_tf32_p(
    float* c,
    uint32_t a0, uint32_t a1, uint32_t a2, uint32_t a3,
    uint32_t b0, uint32_t b1)
{
    asm volatile(
        "mma.sync.aligned.m16n8k8.row.col.f32.tf32.tf32.f32 "
        "{%0,%1,%2,%3},{%4,%5,%6,%7},{%8,%9},{%0,%1,%2,%3};"
        : "+f"(c[0]), "+f"(c[1]), "+f"(c[2]), "+f"(c[3])
        : "r"(a0), "r"(a1), "r"(a2), "r"(a3), "r"(b0), "r"(b1));
}

__device__ __forceinline__ int swz(int r) { return (r & 3) ^ ((r >> 2) & 3); }

// ---------------- RoPE cos/sin table ---------------------------------------
__global__ void rope_table_kernel(const int* __restrict__ pos32)
{
    int idx = blockIdx.x * 256 + threadIdx.x;
    if (idx >= SEQ * 32) return;
    int s = idx >> 5;
    int k = idx & 31;
    const bool is64 = (pos32[1] == 0 && pos32[2] == 1);
    long long pv = is64 ? ((const long long*)pos32)[s] : (long long)pos32[s];
    float p   = (float)pv;
    float inv = powf(10000.0f, -(float)k * (1.0f / 32.0f));
    float sn, cs;
    sincosf(p * inv, &sn, &cs);
    g_rope[idx] = make_float2(cs, sn);
}

// ---------------- tf32 GEMM: C[m,n] = sum_d A[m,d] * W[n,d]  (NT) -----------
// 128x128 tile, BK=16, 256 thr = 8 warps (4m x 2n), warp tile 32x64.
// smem word(r,k) = r*16 + 4*((k&3)^swz(r)) + (k>>2); fragments = 1 LDS.128.
// rope!=0: apply RoPE rotation in the epilogue for blockIdx.z < 2 (Q and K).
// __launch_bounds__(256, 2): cap regs at 128 so 2 CTAs/SM fit (64K-reg RF).
__global__ __launch_bounds__(256, 2) void gemm_tf32_kernel(
    const float* __restrict__ A,
    const float* __restrict__ W0, const float* __restrict__ W1, const float* __restrict__ W2,
    float* __restrict__ C0, float* __restrict__ C1, float* __restrict__ C2,
    int rope)
{
    const float* W; float* C;
    if (blockIdx.z == 0)      { W = W0; C = C0; }
    else if (blockIdx.z == 1) { W = W1; C = C1; }
    else                      { W = W2; C = C2; }

    __shared__ uint32_t As[2][128 * 16];
    __shared__ uint32_t Ws[2][128 * 16];

    const int tid = threadIdx.x;
    const int w  = tid >> 5;
    const int l  = tid & 31;
    const int g  = l >> 2;
    const int tg = l & 3;
    const int m0 = blockIdx.y * 128;
    const int n0 = blockIdx.x * 128;
    const int wm = (w & 3) * 32;
    const int wn = (w >> 2) * 64;

    const int lr = tid >> 1;          // 0..127
    const int lc = (tid & 1) * 8;     // 0 or 8
    const float* Ag = A + (size_t)(m0 + lr) * D_MODEL + lc;
    const float* Wg = W + (size_t)(n0 + lr) * D_MODEL + lc;
    const int srx = swz(lr);
    const int sb  = lr * 16 + (lc >> 2);
    const int e0 = 4 * (0 ^ srx), e1 = 4 * (1 ^ srx), e2 = 4 * (2 ^ srx), e3 = 4 * (3 ^ srx);

    int aoff[2][2], boff[8];
#pragma unroll
    for (int mi = 0; mi < 2; mi++)
#pragma unroll
        for (int hf = 0; hf < 2; hf++) {
            int row = wm + 16 * mi + 8 * hf + g;
            aoff[mi][hf] = row * 16 + 4 * (tg ^ swz(row));
        }
#pragma unroll
    for (int ni = 0; ni < 8; ni++) {
        int row = wn + 8 * ni + g;
        boff[ni] = row * 16 + 4 * (tg ^ swz(row));
    }

    float acc[2][8][4];
#pragma unroll
    for (int mi = 0; mi < 2; mi++)
#pragma unroll
        for (int ni = 0; ni < 8; ni++)
#pragma unroll
            for (int j = 0; j < 4; j++) acc[mi][ni][j] = 0.0f;

    float4 a0v = *(const float4*)Ag;
    float4 a1v = *(const float4*)(Ag + 4);
    float4 w0v = *(const float4*)Wg;
    float4 w1v = *(const float4*)(Wg + 4);

#pragma unroll 1
    for (int t = 0; t < D_MODEL / 16; t++) {
        const int buf = t & 1;
        {
            uint32_t* Ab = As[buf];
            uint32_t* Wb = Ws[buf];
            Ab[sb + e0]     = f2tf(a0v.x);
            Ab[sb + e1]     = f2tf(a0v.y);
            Ab[sb + e2]     = f2tf(a0v.z);
            Ab[sb + e3]     = f2tf(a0v.w);
            Ab[sb + e0 + 1] = f2tf(a1v.x);
            Ab[sb + e1 + 1] = f2tf(a1v.y);
            Ab[sb + e2 + 1] = f2tf(a1v.z);
            Ab[sb + e3 + 1] = f2tf(a1v.w);
            Wb[sb + e0]     = f2tf(w0v.x);
            Wb[sb + e1]     = f2tf(w0v.y);
            Wb[sb + e2]     = f2tf(w0v.z);
            Wb[sb + e3]     = f2tf(w0v.w);
            Wb[sb + e0 + 1] = f2tf(w1v.x);
            Wb[sb + e1 + 1] = f2tf(w1v.y);
            Wb[sb + e2 + 1] = f2tf(w1v.z);
            Wb[sb + e3 + 1] = f2tf(w1v.w);
        }
        __syncthreads();

        if (t + 1 < D_MODEL / 16) {
            const float* An = Ag + (t + 1) * 16;
            const float* Wn = Wg + (t + 1) * 16;
            a0v = *(const float4*)An;
            a1v = *(const float4*)(An + 4);
            w0v = *(const float4*)Wn;
            w1v = *(const float4*)(Wn + 4);
        }

        {
            const uint32_t* Ab = As[buf];
            const uint32_t* Wb = Ws[buf];
            uint4 af[2][2], bf[8];
#pragma unroll
            for (int mi = 0; mi < 2; mi++) {
                af[mi][0] = *(const uint4*)&Ab[aoff[mi][0]];
                af[mi][1] = *(const uint4*)&Ab[aoff[mi][1]];
            }
#pragma unroll
            for (int ni = 0; ni < 8; ni++)
                bf[ni] = *(const uint4*)&Wb[boff[ni]];

#pragma unroll
            for (int mi = 0; mi < 2; mi++)
#pragma unroll
                for (int ni = 0; ni < 8; ni++) {
                    mma_tf32_p(acc[mi][ni],
                               af[mi][0].x, af[mi][1].x, af[mi][0].y, af[mi][1].y,
                               bf[ni].x, bf[ni].y);
                    mma_tf32_p(acc[mi][ni],
                               af[mi][0].z, af[mi][1].z, af[mi][0].w, af[mi][1].w,
                               bf[ni].z, bf[ni].w);
                }
        }
    }

    // fused RoPE (Q and K only): each thread's col pair (2tg, 2tg+1) within an
    // 8ni group is one rotation pair of one head (n offsets are 64-aligned).
    if (rope && blockIdx.z < 2) {
#pragma unroll
        for (int mi = 0; mi < 2; mi++) {
            const int s0 = (m0 + wm + 16 * mi + g) % SEQ;   // row0 % SEQ
            const int s1 = s0 + 8;                          // row1 (no 2048 wrap: block-aligned)
#pragma unroll
            for (int ni = 0; ni < 8; ni++) {
                const int k = ((wn + 8 * ni + 2 * tg) & 63) >> 1;
                float2 cs0 = g_rope[s0 * 32 + k];
                float2 cs1 = g_rope[s1 * 32 + k];
                float xe0 = acc[mi][ni][0], xo0 = acc[mi][ni][1];
                float xe1 = acc[mi][ni][2], xo1 = acc[mi][ni][3];
                acc[mi][ni][0] = cs0.x * xe0 - cs0.y * xo0;
                acc[mi][ni][1] = cs0.y * xe0 + cs0.x * xo0;
                acc[mi][ni][2] = cs1.x * xe1 - cs1.y * xo1;
                acc[mi][ni][3] = cs1.y * xe1 + cs1.x * xo1;
            }
        }
    }

#pragma unroll
    for (int mi = 0; mi < 2; mi++) {
        const size_t row0 = (size_t)(m0 + wm + 16 * mi + g);
        const size_t row1 = row0 + 8;
#pragma unroll
        for (int ni = 0; ni < 8; ni++) {
            const int col = n0 + wn + 8 * ni + 2 * tg;
            *(float2*)(C + row0 * D_MODEL + col) = make_float2(acc[mi][ni][0], acc[mi][ni][1]);
            *(float2*)(C + row1 * D_MODEL + col) = make_float2(acc[mi][ni][2], acc[mi][ni][3]);
        }
    }
}

// ---------------- tf32 tensor-core flash attention -------------------------
// smem (uint32 words): Ks[64][68], Vs[64][72], Ps[64][68]
#define KS_STRIDE 68
#define VS_STRIDE 72
#define PS_STRIDE 68
#define ATTN_SMEM_W (64*KS_STRIDE + 64*VS_STRIDE + 64*PS_STRIDE)
#define ATTN_SMEM_B (ATTN_SMEM_W * 4)

__device__ __forceinline__ void mma_tf32(
    float& c0, float& c1, float& c2, float& c3,
    uint32_t a0, uint32_t a1, uint32_t a2, uint32_t a3,
    uint32_t b0, uint32_t b1)
{
    asm volatile(
        "mma.sync.aligned.m16n8k8.row.col.f32.tf32.tf32.f32 "
        "{%0,%1,%2,%3},{%4,%5,%6,%7},{%8,%9},{%0,%1,%2,%3};"
        : "+f"(c0), "+f"(c1), "+f"(c2), "+f"(c3)
        : "r"(a0), "r"(a1), "r"(a2), "r"(a3), "r"(b0), "r"(b1));
}

__global__ __launch_bounds__(128) void attn_tf32_kernel()
{
    extern __shared__ uint32_t smu[];
    uint32_t* Ks = smu;                                  // [64][68]
    uint32_t* Vs = smu + 64 * KS_STRIDE;                 // [64][72]
    uint32_t* Ps = smu + 64 * KS_STRIDE + 64 * VS_STRIDE;// [64][68]

    const int qb = blockIdx.x, h = blockIdx.y, b = blockIdx.z;
    const int q0 = qb * 64;
    const int tid = threadIdx.x;
    const int w  = tid >> 5;
    const int l  = tid & 31;
    const int g  = l >> 2;
    const int tg = l & 3;

    const float* Qg = g_q + ((size_t)(b * SEQ + q0)) * D_MODEL + h * DKH;
    const float* Kg = g_k + ((size_t)b * SEQ) * D_MODEL + h * DKH;
    const float* Vg = g_v + ((size_t)b * SEQ) * D_MODEL + h * DKH;

    uint32_t qa[8][4];
    {
        const float* r0 = Qg + (size_t)(16 * w + g) * D_MODEL;
        const float* r1 = Qg + (size_t)(16 * w + g + 8) * D_MODEL;
#pragma unroll
        for (int kc = 0; kc < 8; kc++) {
            qa[kc][0] = f2tf(r0[8 * kc + tg]);
            qa[kc][1] = f2tf(r1[8 * kc + tg]);
            qa[kc][2] = f2tf(r0[8 * kc + tg + 4]);
            qa[kc][3] = f2tf(r1[8 * kc + tg + 4]);
        }
    }

    float o[8][4];
#pragma unroll
    for (int dc = 0; dc < 8; dc++)
#pragma unroll
        for (int j = 0; j < 4; j++) o[dc][j] = 0.0f;
    float m0 = -1e30f, m1 = -1e30f, l0 = 0.0f, l1 = 0.0f;

    for (int kb = 0; kb <= qb; kb++) {
        const int k0 = kb * 64;
        __syncthreads();
#pragma unroll
        for (int i = 0; i < 8; i++) {
            int idx = tid + 128 * i;
            int r   = idx >> 4;
            int c   = (idx & 15) * 4;
            float4 kv = *(const float4*)(Kg + (size_t)(k0 + r) * D_MODEL + c);
            float4 vv = *(const float4*)(Vg + (size_t)(k0 + r) * D_MODEL + c);
            uint4 kt = make_uint4(f2tf(kv.x), f2tf(kv.y), f2tf(kv.z), f2tf(kv.w));
            uint4 vt = make_uint4(f2tf(vv.x), f2tf(vv.y), f2tf(vv.z), f2tf(vv.w));
            *(uint4*)&Ks[r * KS_STRIDE + c] = kt;
            *(uint4*)&Vs[r * VS_STRIDE + c] = vt;
        }
        __syncthreads();

        float s[8][4];
#pragma unroll
        for (int nc = 0; nc < 8; nc++)
#pragma unroll
            for (int j = 0; j < 4; j++) s[nc][j] = 0.0f;

#pragma unroll
        for (int nc = 0; nc < 8; nc++) {
            const uint32_t* krow = &Ks[(8 * nc + g) * KS_STRIDE];
#pragma unroll
            for (int kc = 0; kc < 8; kc++) {
                uint32_t b0 = krow[8 * kc + tg];
                uint32_t b1 = krow[8 * kc + tg + 4];
                mma_tf32(s[nc][0], s[nc][1], s[nc][2], s[nc][3],
                         qa[kc][0], qa[kc][1], qa[kc][2], qa[kc][3], b0, b1);
            }
        }

#pragma unroll
        for (int nc = 0; nc < 8; nc++)
#pragma unroll
            for (int j = 0; j < 4; j++) s[nc][j] *= 0.125f;

        if (kb == qb) {
            const int r0 = 16 * w + g, r1 = r0 + 8;
#pragma unroll
            for (int nc = 0; nc < 8; nc++) {
                int c0 = 8 * nc + 2 * tg, c1 = c0 + 1;
                if (c0 > r0) s[nc][0] = -1e30f;
                if (c1 > r0) s[nc][1] = -1e30f;
                if (c0 > r1) s[nc][2] = -1e30f;
                if (c1 > r1) s[nc][3] = -1e30f;
            }
        }

        float rm0 = -1e30f, rm1 = -1e30f;
#pragma unroll
        for (int nc = 0; nc < 8; nc++) {
            rm0 = fmaxf(rm0, fmaxf(s[nc][0], s[nc][1]));
            rm1 = fmaxf(rm1, fmaxf(s[nc][2], s[nc][3]));
        }
        rm0 = fmaxf(rm0, __shfl_xor_sync(0xffffffffu, rm0, 1));
        rm0 = fmaxf(rm0, __shfl_xor_sync(0xffffffffu, rm0, 2));
        rm1 = fmaxf(rm1, __shfl_xor_sync(0xffffffffu, rm1, 1));
        rm1 = fmaxf(rm1, __shfl_xor_sync(0xffffffffu, rm1, 2));

        float mn0 = fmaxf(m0, rm0), mn1 = fmaxf(m1, rm1);
        float al0 = __expf(m0 - mn0), al1 = __expf(m1 - mn1);
        m0 = mn0; m1 = mn1;

        float rs0 = 0.0f, rs1 = 0.0f;
#pragma unroll
        for (int nc = 0; nc < 8; nc++) {
            float p0 = __expf(s[nc][0] - mn0);
            float p1 = __expf(s[nc][1] - mn0);
            float p2 = __expf(s[nc][2] - mn1);
            float p3 = __expf(s[nc][3] - mn1);
            s[nc][0] = p0; s[nc][1] = p1; s[nc][2] = p2; s[nc][3] = p3;
            rs0 += p0 + p1; rs1 += p2 + p3;
        }
        rs0 += __shfl_xor_sync(0xffffffffu, rs0, 1);
        rs0 += __shfl_xor_sync(0xffffffffu, rs0, 2);
        rs1 += __shfl_xor_sync(0xffffffffu, rs1, 1);
        rs1 += __shfl_xor_sync(0xffffffffu, rs1, 2);
        l0 = l0 * al0 + rs0;
        l1 = l1 * al1 + rs1;

#pragma unroll
        for (int dc = 0; dc < 8; dc++) {
            o[dc][0] *= al0; o[dc][1] *= al0;
            o[dc][2] *= al1; o[dc][3] *= al1;
        }

        {
            const int r0 = 16 * w + g, r1 = r0 + 8;
#pragma unroll
            for (int nc = 0; nc < 8; nc++) {
                uint2 p01 = make_uint2(f2tf(s[nc][0]), f2tf(s[nc][1]));
                uint2 p23 = make_uint2(f2tf(s[nc][2]), f2tf(s[nc][3]));
                *(uint2*)&Ps[r0 * PS_STRIDE + 8 * nc + 2 * tg] = p01;
                *(uint2*)&Ps[r1 * PS_STRIDE + 8 * nc + 2 * tg] = p23;
            }
        }
        __syncwarp();

        uint32_t pa[8][4];
        {
            const uint32_t* p0 = &Ps[(16 * w + g) * PS_STRIDE];
            const uint32_t* p1 = &Ps[(16 * w + g + 8) * PS_STRIDE];
#pragma unroll
            for (int nc = 0; nc < 8; nc++) {
                pa[nc][0] = p0[8 * nc + tg];
                pa[nc][1] = p1[8 * nc + tg];
                pa[nc][2] = p0[8 * nc + tg + 4];
                pa[nc][3] = p1[8 * nc + tg + 4];
            }
        }

#pragma unroll
        for (int dc = 0; dc < 8; dc++) {
#pragma unroll
            for (int nc = 0; nc < 8; nc++) {
                uint32_t b0 = Vs[(8 * nc + tg) * VS_STRIDE + 8 * dc + g];
                uint32_t b1 = Vs[(8 * nc + tg + 4) * VS_STRIDE + 8 * dc + g];
                mma_tf32(o[dc][0], o[dc][1], o[dc][2], o[dc][3],
                         pa[nc][0], pa[nc][1], pa[nc][2], pa[nc][3], b0, b1);
            }
        }
    }

    float* Og = g_ctx + ((size_t)(b * SEQ + q0)) * D_MODEL + h * DKH;
    float il0 = 1.0f / l0, il1 = 1.0f / l1;
    float* w0 = Og + (size_t)(16 * w + g) * D_MODEL;
    float* w1 = Og + (size_t)(16 * w + g + 8) * D_MODEL;
#pragma unroll
    for (int dc = 0; dc < 8; dc++) {
        *(float2*)(w0 + 8 * dc + 2 * tg) = make_float2(o[dc][0] * il0, o[dc][1] * il0);
        *(float2*)(w1 + 8 * dc + 2 * tg) = make_float2(o[dc][2] * il1, o[dc][3] * il1);
    }
}

// ---------------- launch ---------------------------------------------------
extern "C" void kernel_launch(void* const* d_in, const int* in_sizes, int n_in,
                              void* d_out, int out_size)
{
    const float*      X   = (const float*)d_in[0];
    const int*        pos = (const int*)d_in[1];
    const float*      Wq  = (const float*)d_in[2];
    const float*      Wk  = (const float*)d_in[3];
    const float*      Wv  = (const float*)d_in[4];
    const float*      Wo  = (const float*)d_in[5];
    float*            out = (float*)d_out;

    float *dq, *dk, *dv, *dctx;
    cudaGetSymbolAddress((void**)&dq,   g_q);
    cudaGetSymbolAddress((void**)&dk,   g_k);
    cudaGetSymbolAddress((void**)&dv,   g_v);
    cudaGetSymbolAddress((void**)&dctx, g_ctx);

    // RoPE cos/sin table
    rope_table_kernel<<<(SEQ * 32 + 255) / 256, 256>>>(pos);

    // QKV projections (tf32 tensor cores) with fused RoPE on Q, K
    dim3 gqkv(D_MODEL / 128, MT / 128, 3);
    gemm_tf32_kernel<<<gqkv, 256>>>(X, Wq, Wk, Wv, dq, dk, dv, 1);

    // causal attention (tf32 tensor cores)
    cudaFuncSetAttribute(attn_tf32_kernel, cudaFuncAttributeMaxDynamicSharedMemorySize, ATTN_SMEM_B);
    dim3 ga(SEQ / 64, NHEADS, BATCH);
    attn_tf32_kernel<<<ga, 128, ATTN_SMEM_B>>>();

    // output projection (tf32 tensor cores, no rope)
    dim3 go(D_MODEL / 128, MT / 128, 1);
    gemm_tf32_kernel<<<go, 256>>>(dctx, Wo, Wo, Wo, out, out, out, 0);
}

// round 12
// speedup vs baseline: 1.2239x; 1.1730x over previous
#include <cuda_runtime.h>
#include <math.h>
#include <stdint.h>

#define D_MODEL 1024
#define NHEADS  16
#define DKH     64
#define BATCH   4
#define SEQ     2048
#define MT      (BATCH*SEQ)   // 8192 rows

// ---------------- scratch (device globals; no cudaMalloc allowed) ----------
__device__ float g_q[(size_t)MT * D_MODEL];
__device__ float g_k[(size_t)MT * D_MODEL];
__device__ float g_v[(size_t)MT * D_MODEL];
__device__ float g_ctx[(size_t)MT * D_MODEL];
__device__ float2 g_rope[(size_t)SEQ * 32];   // [s][k] -> (cos, sin)

// ---------------- helpers ---------------------------------------------------
__device__ __forceinline__ uint32_t f2tf(float x) {
    uint32_t r;
    asm("cvt.rna.tf32.f32 %0, %1;" : "=r"(r) : "f"(x));
    return r;
}

__device__ __forceinline__ void mma_tf32_p(
    float* c,
    uint32_t a0, uint32_t a1, uint32_t a2, uint32_t a3,
    uint32_t b0, uint32_t b1)
{
    asm volatile(
        "mma.sync.aligned.m16n8k8.row.col.f32.tf32.tf32.f32 "
        "{%0,%1,%2,%3},{%4,%5,%6,%7},{%8,%9},{%0,%1,%2,%3};"
        : "+f"(c[0]), "+f"(c[1]), "+f"(c[2]), "+f"(c[3])
        : "r"(a0), "r"(a1), "r"(a2), "r"(a3), "r"(b0), "r"(b1));
}

__device__ __forceinline__ int swz(int r) { return (r & 3) ^ ((r >> 2) & 3); }

// ---------------- RoPE cos/sin table (tiny; transcendentals once) ----------
__global__ void rope_table_kernel(const int* __restrict__ pos32)
{
    int idx = blockIdx.x * 256 + threadIdx.x;
    if (idx >= SEQ * 32) return;
    int s = idx >> 5;
    int k = idx & 31;
    const bool is64 = (pos32[1] == 0 && pos32[2] == 1);
    long long pv = is64 ? ((const long long*)pos32)[s] : (long long)pos32[s];
    float p   = (float)pv;
    float inv = powf(10000.0f, -(float)k * (1.0f / 32.0f));
    float sn, cs;
    sincosf(p * inv, &sn, &cs);
    g_rope[idx] = make_float2(cs, sn);
}

// ---------------- RoPE apply (table-based, float4 = 2 pairs / thread) ------
__global__ void rope_apply_kernel()
{
    const size_t QUADS = (size_t)MT * (D_MODEL / 4);
    size_t idx = (size_t)blockIdx.x * blockDim.x + threadIdx.x;
    if (idx >= QUADS) return;
    float* X = (blockIdx.y == 0) ? g_q : g_k;

    const int m = (int)(idx >> 8);          // row (D_MODEL/4 = 256 quads per row)
    const int c4 = (int)(idx & 255);        // quad index within row
    const int col = c4 * 4;                 // element column
    const int k0 = (col & 63) >> 1;         // head-local pair index of first pair
    const int s  = m & (SEQ - 1);           // m % SEQ

    float2 cs0 = g_rope[s * 32 + k0];
    float2 cs1 = g_rope[s * 32 + k0 + 1];

    float4 v = *(float4*)(X + (size_t)m * D_MODEL + col);
    float4 r;
    r.x = cs0.x * v.x - cs0.y * v.y;
    r.y = cs0.y * v.x + cs0.x * v.y;
    r.z = cs1.x * v.z - cs1.y * v.w;
    r.w = cs1.y * v.z + cs1.x * v.w;
    *(float4*)(X + (size_t)m * D_MODEL + col) = r;
}

// ---------------- tf32 GEMM: C[m,n] = sum_d A[m,d] * W[n,d]  (NT) -----------
// 128x128 tile, BK=16, 256 thr = 8 warps (4m x 2n), warp tile 32x64.
// smem word(r,k) = r*16 + 4*((k&3)^swz(r)) + (k>>2); fragments = 1 LDS.128.
// Exactly the proven R7 kernel (183us/launch, regs=128, 2 CTAs/SM).
__global__ __launch_bounds__(256) void gemm_tf32_kernel(
    const float* __restrict__ A,
    const float* __restrict__ W0, const float* __restrict__ W1, const float* __restrict__ W2,
    float* __restrict__ C0, float* __restrict__ C1, float* __restrict__ C2)
{
    const float* W; float* C;
    if (blockIdx.z == 0)      { W = W0; C = C0; }
    else if (blockIdx.z == 1) { W = W1; C = C1; }
    else                      { W = W2; C = C2; }

    __shared__ uint32_t As[2][128 * 16];
    __shared__ uint32_t Ws[2][128 * 16];

    const int tid = threadIdx.x;
    const int w  = tid >> 5;
    const int l  = tid & 31;
    const int g  = l >> 2;
    const int tg = l & 3;
    const int m0 = blockIdx.y * 128;
    const int n0 = blockIdx.x * 128;
    const int wm = (w & 3) * 32;
    const int wn = (w >> 2) * 64;

    const int lr = tid >> 1;          // 0..127
    const int lc = (tid & 1) * 8;     // 0 or 8
    const float* Ag = A + (size_t)(m0 + lr) * D_MODEL + lc;
    const float* Wg = W + (size_t)(n0 + lr) * D_MODEL + lc;
    const int srx = swz(lr);
    const int sb  = lr * 16 + (lc >> 2);
    const int e0 = 4 * (0 ^ srx), e1 = 4 * (1 ^ srx), e2 = 4 * (2 ^ srx), e3 = 4 * (3 ^ srx);

    int aoff[2][2], boff[8];
#pragma unroll
    for (int mi = 0; mi < 2; mi++)
#pragma unroll
        for (int hf = 0; hf < 2; hf++) {
            int row = wm + 16 * mi + 8 * hf + g;
            aoff[mi][hf] = row * 16 + 4 * (tg ^ swz(row));
        }
#pragma unroll
    for (int ni = 0; ni < 8; ni++) {
        int row = wn + 8 * ni + g;
        boff[ni] = row * 16 + 4 * (tg ^ swz(row));
    }

    float acc[2][8][4];
#pragma unroll
    for (int mi = 0; mi < 2; mi++)
#pragma unroll
        for (int ni = 0; ni < 8; ni++)
#pragma unroll
            for (int j = 0; j < 4; j++) acc[mi][ni][j] = 0.0f;

    float4 a0v = *(const float4*)Ag;
    float4 a1v = *(const float4*)(Ag + 4);
    float4 w0v = *(const float4*)Wg;
    float4 w1v = *(const float4*)(Wg + 4);

#pragma unroll 1
    for (int t = 0; t < D_MODEL / 16; t++) {
        const int buf = t & 1;
        {
            uint32_t* Ab = As[buf];
            uint32_t* Wb = Ws[buf];
            Ab[sb + e0]     = f2tf(a0v.x);
            Ab[sb + e1]     = f2tf(a0v.y);
            Ab[sb + e2]     = f2tf(a0v.z);
            Ab[sb + e3]     = f2tf(a0v.w);
            Ab[sb + e0 + 1] = f2tf(a1v.x);
            Ab[sb + e1 + 1] = f2tf(a1v.y);
            Ab[sb + e2 + 1] = f2tf(a1v.z);
            Ab[sb + e3 + 1] = f2tf(a1v.w);
            Wb[sb + e0]     = f2tf(w0v.x);
            Wb[sb + e1]     = f2tf(w0v.y);
            Wb[sb + e2]     = f2tf(w0v.z);
            Wb[sb + e3]     = f2tf(w0v.w);
            Wb[sb + e0 + 1] = f2tf(w1v.x);
            Wb[sb + e1 + 1] = f2tf(w1v.y);
            Wb[sb + e2 + 1] = f2tf(w1v.z);
            Wb[sb + e3 + 1] = f2tf(w1v.w);
        }
        __syncthreads();

        if (t + 1 < D_MODEL / 16) {
            const float* An = Ag + (t + 1) * 16;
            const float* Wn = Wg + (t + 1) * 16;
            a0v = *(const float4*)An;
            a1v = *(const float4*)(An + 4);
            w0v = *(const float4*)Wn;
            w1v = *(const float4*)(Wn + 4);
        }

        {
            const uint32_t* Ab = As[buf];
            const uint32_t* Wb = Ws[buf];
            uint4 af[2][2], bf[8];
#pragma unroll
            for (int mi = 0; mi < 2; mi++) {
                af[mi][0] = *(const uint4*)&Ab[aoff[mi][0]];
                af[mi][1] = *(const uint4*)&Ab[aoff[mi][1]];
            }
#pragma unroll
            for (int ni = 0; ni < 8; ni++)
                bf[ni] = *(const uint4*)&Wb[boff[ni]];

#pragma unroll
            for (int mi = 0; mi < 2; mi++)
#pragma unroll
                for (int ni = 0; ni < 8; ni++) {
                    mma_tf32_p(acc[mi][ni],
                               af[mi][0].x, af[mi][1].x, af[mi][0].y, af[mi][1].y,
                               bf[ni].x, bf[ni].y);
                    mma_tf32_p(acc[mi][ni],
                               af[mi][0].z, af[mi][1].z, af[mi][0].w, af[mi][1].w,
                               bf[ni].z, bf[ni].w);
                }
        }
    }

#pragma unroll
    for (int mi = 0; mi < 2; mi++) {
        const size_t row0 = (size_t)(m0 + wm + 16 * mi + g);
        const size_t row1 = row0 + 8;
#pragma unroll
        for (int ni = 0; ni < 8; ni++) {
            const int col = n0 + wn + 8 * ni + 2 * tg;
            *(float2*)(C + row0 * D_MODEL + col) = make_float2(acc[mi][ni][0], acc[mi][ni][1]);
            *(float2*)(C + row1 * D_MODEL + col) = make_float2(acc[mi][ni][2], acc[mi][ni][3]);
        }
    }
}

// ---------------- tf32 tensor-core flash attention -------------------------
// smem (uint32 words): Ks[64][68], Vs[64][72], Ps[64][68]
#define KS_STRIDE 68
#define VS_STRIDE 72
#define PS_STRIDE 68
#define ATTN_SMEM_W (64*KS_STRIDE + 64*VS_STRIDE + 64*PS_STRIDE)
#define ATTN_SMEM_B (ATTN_SMEM_W * 4)

__device__ __forceinline__ void mma_tf32(
    float& c0, float& c1, float& c2, float& c3,
    uint32_t a0, uint32_t a1, uint32_t a2, uint32_t a3,
    uint32_t b0, uint32_t b1)
{
    asm volatile(
        "mma.sync.aligned.m16n8k8.row.col.f32.tf32.tf32.f32 "
        "{%0,%1,%2,%3},{%4,%5,%6,%7},{%8,%9},{%0,%1,%2,%3};"
        : "+f"(c0), "+f"(c1), "+f"(c2), "+f"(c3)
        : "r"(a0), "r"(a1), "r"(a2), "r"(a3), "r"(b0), "r"(b1));
}

__global__ __launch_bounds__(128) void attn_tf32_kernel()
{
    extern __shared__ uint32_t smu[];
    uint32_t* Ks = smu;                                  // [64][68]
    uint32_t* Vs = smu + 64 * KS_STRIDE;                 // [64][72]
    uint32_t* Ps = smu + 64 * KS_STRIDE + 64 * VS_STRIDE;// [64][68]

    const int qb = blockIdx.x, h = blockIdx.y, b = blockIdx.z;
    const int q0 = qb * 64;
    const int tid = threadIdx.x;
    const int w  = tid >> 5;
    const int l  = tid & 31;
    const int g  = l >> 2;
    const int tg = l & 3;

    const float* Qg = g_q + ((size_t)(b * SEQ + q0)) * D_MODEL + h * DKH;
    const float* Kg = g_k + ((size_t)b * SEQ) * D_MODEL + h * DKH;
    const float* Vg = g_v + ((size_t)b * SEQ) * D_MODEL + h * DKH;

    uint32_t qa[8][4];
    {
        const float* r0 = Qg + (size_t)(16 * w + g) * D_MODEL;
        const float* r1 = Qg + (size_t)(16 * w + g + 8) * D_MODEL;
#pragma unroll
        for (int kc = 0; kc < 8; kc++) {
            qa[kc][0] = f2tf(r0[8 * kc + tg]);
            qa[kc][1] = f2tf(r1[8 * kc + tg]);
            qa[kc][2] = f2tf(r0[8 * kc + tg + 4]);
            qa[kc][3] = f2tf(r1[8 * kc + tg + 4]);
        }
    }

    float o[8][4];
#pragma unroll
    for (int dc = 0; dc < 8; dc++)
#pragma unroll
        for (int j = 0; j < 4; j++) o[dc][j] = 0.0f;
    float m0 = -1e30f, m1 = -1e30f, l0 = 0.0f, l1 = 0.0f;

    for (int kb = 0; kb <= qb; kb++) {
        const int k0 = kb * 64;
        __syncthreads();
#pragma unroll
        for (int i = 0; i < 8; i++) {
            int idx = tid + 128 * i;
            int r   = idx >> 4;
            int c   = (idx & 15) * 4;
            float4 kv = *(const float4*)(Kg + (size_t)(k0 + r) * D_MODEL + c);
            float4 vv = *(const float4*)(Vg + (size_t)(k0 + r) * D_MODEL + c);
            uint4 kt = make_uint4(f2tf(kv.x), f2tf(kv.y), f2tf(kv.z), f2tf(kv.w));
            uint4 vt = make_uint4(f2tf(vv.x), f2tf(vv.y), f2tf(vv.z), f2tf(vv.w));
            *(uint4*)&Ks[r * KS_STRIDE + c] = kt;
            *(uint4*)&Vs[r * VS_STRIDE + c] = vt;
        }
        __syncthreads();

        float s[8][4];
#pragma unroll
        for (int nc = 0; nc < 8; nc++)
#pragma unroll
            for (int j = 0; j < 4; j++) s[nc][j] = 0.0f;

#pragma unroll
        for (int nc = 0; nc < 8; nc++) {
            const uint32_t* krow = &Ks[(8 * nc + g) * KS_STRIDE];
#pragma unroll
            for (int kc = 0; kc < 8; kc++) {
                uint32_t b0 = krow[8 * kc + tg];
                uint32_t b1 = krow[8 * kc + tg + 4];
                mma_tf32(s[nc][0], s[nc][1], s[nc][2], s[nc][3],
                         qa[kc][0], qa[kc][1], qa[kc][2], qa[kc][3], b0, b1);
            }
        }

#pragma unroll
        for (int nc = 0; nc < 8; nc++)
#pragma unroll
            for (int j = 0; j < 4; j++) s[nc][j] *= 0.125f;

        if (kb == qb) {
            const int r0 = 16 * w + g, r1 = r0 + 8;
#pragma unroll
            for (int nc = 0; nc < 8; nc++) {
                int c0 = 8 * nc + 2 * tg, c1 = c0 + 1;
                if (c0 > r0) s[nc][0] = -1e30f;
                if (c1 > r0) s[nc][1] = -1e30f;
                if (c0 > r1) s[nc][2] = -1e30f;
                if (c1 > r1) s[nc][3] = -1e30f;
            }
        }

        float rm0 = -1e30f, rm1 = -1e30f;
#pragma unroll
        for (int nc = 0; nc < 8; nc++) {
            rm0 = fmaxf(rm0, fmaxf(s[nc][0], s[nc][1]));
            rm1 = fmaxf(rm1, fmaxf(s[nc][2], s[nc][3]));
        }
        rm0 = fmaxf(rm0, __shfl_xor_sync(0xffffffffu, rm0, 1));
        rm0 = fmaxf(rm0, __shfl_xor_sync(0xffffffffu, rm0, 2));
        rm1 = fmaxf(rm1, __shfl_xor_sync(0xffffffffu, rm1, 1));
        rm1 = fmaxf(rm1, __shfl_xor_sync(0xffffffffu, rm1, 2));

        float mn0 = fmaxf(m0, rm0), mn1 = fmaxf(m1, rm1);
        float al0 = __expf(m0 - mn0), al1 = __expf(m1 - mn1);
        m0 = mn0; m1 = mn1;

        float rs0 = 0.0f, rs1 = 0.0f;
#pragma unroll
        for (int nc = 0; nc < 8; nc++) {
            float p0 = __expf(s[nc][0] - mn0);
            float p1 = __expf(s[nc][1] - mn0);
            float p2 = __expf(s[nc][2] - mn1);
            float p3 = __expf(s[nc][3] - mn1);
            s[nc][0] = p0; s[nc][1] = p1; s[nc][2] = p2; s[nc][3] = p3;
            rs0 += p0 + p1; rs1 += p2 + p3;
        }
        rs0 += __shfl_xor_sync(0xffffffffu, rs0, 1);
        rs0 += __shfl_xor_sync(0xffffffffu, rs0, 2);
        rs1 += __shfl_xor_sync(0xffffffffu, rs1, 1);
        rs1 += __shfl_xor_sync(0xffffffffu, rs1, 2);
        l0 = l0 * al0 + rs0;
        l1 = l1 * al1 + rs1;

#pragma unroll
        for (int dc = 0; dc < 8; dc++) {
            o[dc][0] *= al0; o[dc][1] *= al0;
            o[dc][2] *= al1; o[dc][3] *= al1;
        }

        {
            const int r0 = 16 * w + g, r1 = r0 + 8;
#pragma unroll
            for (int nc = 0; nc < 8; nc++) {
                uint2 p01 = make_uint2(f2tf(s[nc][0]), f2tf(s[nc][1]));
                uint2 p23 = make_uint2(f2tf(s[nc][2]), f2tf(s[nc][3]));
                *(uint2*)&Ps[r0 * PS_STRIDE + 8 * nc + 2 * tg] = p01;
                *(uint2*)&Ps[r1 * PS_STRIDE + 8 * nc + 2 * tg] = p23;
            }
        }
        __syncwarp();

        uint32_t pa[8][4];
        {
            const uint32_t* p0 = &Ps[(16 * w + g) * PS_STRIDE];
            const uint32_t* p1 = &Ps[(16 * w + g + 8) * PS_STRIDE];
#pragma unroll
            for (int nc = 0; nc < 8; nc++) {
                pa[nc][0] = p0[8 * nc + tg];
                pa[nc][1] = p1[8 * nc + tg];
                pa[nc][2] = p0[8 * nc + tg + 4];
                pa[nc][3] = p1[8 * nc + tg + 4];
            }
        }

#pragma unroll
        for (int dc = 0; dc < 8; dc++) {
#pragma unroll
            for (int nc = 0; nc < 8; nc++) {
                uint32_t b0 = Vs[(8 * nc + tg) * VS_STRIDE + 8 * dc + g];
                uint32_t b1 = Vs[(8 * nc + tg + 4) * VS_STRIDE + 8 * dc + g];
                mma_tf32(o[dc][0], o[dc][1], o[dc][2], o[dc][3],
                         pa[nc][0], pa[nc][1], pa[nc][2], pa[nc][3], b0, b1);
            }
        }
    }

    float* Og = g_ctx + ((size_t)(b * SEQ + q0)) * D_MODEL + h * DKH;
    float il0 = 1.0f / l0, il1 = 1.0f / l1;
    float* w0 = Og + (size_t)(16 * w + g) * D_MODEL;
    float* w1 = Og + (size_t)(16 * w + g + 8) * D_MODEL;
#pragma unroll
    for (int dc = 0; dc < 8; dc++) {
        *(float2*)(w0 + 8 * dc + 2 * tg) = make_float2(o[dc][0] * il0, o[dc][1] * il0);
        *(float2*)(w1 + 8 * dc + 2 * tg) = make_float2(o[dc][2] * il1, o[dc][3] * il1);
    }
}

// ---------------- launch ---------------------------------------------------
extern "C" void kernel_launch(void* const* d_in, const int* in_sizes, int n_in,
                              void* d_out, int out_size)
{
    const float*      X   = (const float*)d_in[0];
    const int*        pos = (const int*)d_in[1];
    const float*      Wq  = (const float*)d_in[2];
    const float*      Wk  = (const float*)d_in[3];
    const float*      Wv  = (const float*)d_in[4];
    const float*      Wo  = (const float*)d_in[5];
    float*            out = (float*)d_out;

    float *dq, *dk, *dv, *dctx;
    cudaGetSymbolAddress((void**)&dq,   g_q);
    cudaGetSymbolAddress((void**)&dk,   g_k);
    cudaGetSymbolAddress((void**)&dv,   g_v);
    cudaGetSymbolAddress((void**)&dctx, g_ctx);

    // RoPE table (transcendentals once: 64K entries)
    rope_table_kernel<<<(SEQ * 32 + 255) / 256, 256>>>(pos);

    // QKV projections (tf32 tensor cores, clean R7 kernel)
    dim3 gqkv(D_MODEL / 128, MT / 128, 3);
    gemm_tf32_kernel<<<gqkv, 256>>>(X, Wq, Wk, Wv, dq, dk, dv);

    // RoPE applied to Q and K from the table (streaming, float4/thread)
    dim3 gr((unsigned)(((size_t)MT * (D_MODEL / 4) + 255) / 256), 2, 1);
    rope_apply_kernel<<<gr, 256>>>();

    // causal attention (tf32 tensor cores)
    cudaFuncSetAttribute(attn_tf32_kernel, cudaFuncAttributeMaxDynamicSharedMemorySize, ATTN_SMEM_B);
    dim3 ga(SEQ / 64, NHEADS, BATCH);
    attn_tf32_kernel<<<ga, 128, ATTN_SMEM_B>>>();

    // output projection (tf32 tensor cores)
    dim3 go(D_MODEL / 128, MT / 128, 1);
    gemm_tf32_kernel<<<go, 256>>>(dctx, Wo, Wo, Wo, out, out, out);
}